// round 16
// baseline (speedup 1.0000x reference)
#include <cuda_runtime.h>
#include <cuda_fp16.h>
#include <cstdint>

#define Bn  4
#define Sn  1024
#define DMn 1024
#define Hn  16
#define DKn 64

// Scratch (allocation-free rule: __device__ globals). All half.
__device__ __half g_Xh[(size_t)Bn * Sn * DMn];        // X in half
__device__ __half g_Qh[(size_t)Bn * Hn * Sn * DKn];   // pre-scaled by 0.125*log2e
__device__ __half g_Kh[(size_t)Bn * Hn * Sn * DKn];
__device__ __half g_Vh[(size_t)Bn * Hn * Sn * DKn];
__device__ __half g_Zh[(size_t)Bn * Sn * Hn * DKn];   // [b,s,h*64+v]
// K-major half weights: rows n, cols d.
//   n in [0,1024): Q | [1024,2048): K | [2048,3072): V | [3072,4096): Wo col
__device__ __half g_Wth[(size_t)4096 * 1024];

__device__ __forceinline__ uint32_t smem_u32(const void* p) {
    uint32_t a;
    asm("{ .reg .u64 t; cvta.to.shared.u64 t, %1; cvt.u32.u64 %0, t; }"
        : "=r"(a) : "l"(p));
    return a;
}
__device__ __forceinline__ void cp16(uint32_t dst, const void* src) {
    asm volatile("cp.async.cg.shared.global [%0], [%1], 16;"
                 :: "r"(dst), "l"(src));
}
__device__ __forceinline__ void cp_commit() {
    asm volatile("cp.async.commit_group;");
}
template <int N>
__device__ __forceinline__ void cp_wait() {
    asm volatile("cp.async.wait_group %0;" :: "n"(N));
}
__device__ __forceinline__ void ldsm_x4(uint32_t* r, uint32_t addr) {
    asm volatile("ldmatrix.sync.aligned.m8n8.x4.shared.b16 {%0,%1,%2,%3}, [%4];"
                 : "=r"(r[0]), "=r"(r[1]), "=r"(r[2]), "=r"(r[3]) : "r"(addr));
}
__device__ __forceinline__ void ldsm_x4t(uint32_t* r, uint32_t addr) {
    asm volatile("ldmatrix.sync.aligned.m8n8.x4.trans.shared.b16 {%0,%1,%2,%3}, [%4];"
                 : "=r"(r[0]), "=r"(r[1]), "=r"(r[2]), "=r"(r[3]) : "r"(addr));
}
__device__ __forceinline__ float ex2f(float x) {
    float y;
    asm("ex2.approx.f32 %0, %1;" : "=f"(y) : "f"(x));
    return y;
}

// fp16 mma: m16n8k16, f32 accumulate.
__device__ __forceinline__ void mma_f16(float* c, const uint32_t* a, const uint32_t* b) {
    asm volatile(
        "mma.sync.aligned.m16n8k16.row.col.f32.f16.f16.f32 "
        "{%0,%1,%2,%3}, {%4,%5,%6,%7}, {%8,%9}, {%0,%1,%2,%3};"
        : "+f"(c[0]), "+f"(c[1]), "+f"(c[2]), "+f"(c[3])
        : "r"(a[0]), "r"(a[1]), "r"(a[2]), "r"(a[3]), "r"(b[0]), "r"(b[1]));
}

// ---------------------------------------------------------------------------
// Kernel 0 (fused prep): blocks [0,1024) convert X->half (16 elems/thread);
// blocks [1024,5120) transpose weights to K-major half.
// ---------------------------------------------------------------------------
__global__ __launch_bounds__(256) void prep_kernel(
    const float* __restrict__ X,
    const float* __restrict__ Wq, const float* __restrict__ Wk,
    const float* __restrict__ Wv, const float* __restrict__ Wo)
{
    int blk = blockIdx.x;
    int tid = threadIdx.x;
    if (blk < 1024) {
        size_t base = ((size_t)blk * 256 + tid) * 16;
        #pragma unroll
        for (int j = 0; j < 4; j++) {
            float4 v = *reinterpret_cast<const float4*>(&X[base + j * 4]);
            __half2 h0 = __floats2half2_rn(v.x, v.y);
            __half2 h1 = __floats2half2_rn(v.z, v.w);
            uint2 pk;
            pk.x = *reinterpret_cast<uint32_t*>(&h0);
            pk.y = *reinterpret_cast<uint32_t*>(&h1);
            *reinterpret_cast<uint2*>(&g_Xh[base + j * 4]) = pk;
        }
        return;
    }
    __shared__ float t[32][33];
    int bid = blk - 1024;
    int bx  = bid & 127;
    int by  = bid >> 7;
    int n0 = bx * 32;
    int d0 = by * 32;
    int r  = n0 >> 10;

    #pragma unroll
    for (int p = 0; p < 4; p++) {
        int idx = p * 256 + tid;
        int dl  = idx >> 5;
        int j   = idx & 31;
        int d   = d0 + dl;
        float v;
        if (r < 3) {
            int hh = (n0 >> 6) & 15;
            int k0 = n0 & 63;
            const float* W = (r == 0) ? Wq : (r == 1) ? Wk : Wv;
            v = W[(size_t)hh * 65536 + (size_t)d * 64 + k0 + j];
        } else {
            v = Wo[(size_t)d * 1024 + (n0 - 3072) + j];
        }
        t[dl][j] = v;
    }
    __syncthreads();
    #pragma unroll
    for (int p = 0; p < 4; p++) {
        int idx = p * 256 + tid;
        int nl  = idx >> 5;
        int dd  = idx & 31;
        g_Wth[(size_t)(n0 + nl) * 1024 + d0 + dd] = __float2half_rn(t[dd][nl]);
    }
}

// ---------------------------------------------------------------------------
// fp16 mma GEMM: BM=128, BN=128, 8 warps (2m x 4n), K-chunk=64, 16 chunks,
// 3-stage cp.async ring, 2 CTAs/SM. Per-warp ks AND mt rotation (port desync),
// cp.async issues spread across ks steps.
// ---------------------------------------------------------------------------
#define HStr 72
#define GEMM_STAGE_B ((128 + 128) * HStr * 2)
#define GEMM_SMEM    (3 * GEMM_STAGE_B)

template <int MODE>
__global__ __launch_bounds__(256, 2) void gemm_mma_kernel(
    const float* __restrict__ b0, const float* __restrict__ b1,
    const float* __restrict__ b2,
    const float* __restrict__ Xres, float* __restrict__ Out)
{
    extern __shared__ __half smh[];
    const uint32_t s0 = smem_u32(smh);
    const uint32_t bHalfOff = 128 * HStr * 2;

    const int tid  = threadIdx.x;
    const int wid  = tid >> 5;
    const int lane = tid & 31;
    const int grp  = lane >> 2;
    const int tig  = lane & 3;
    const int wm   = wid & 1;
    const int wn   = wid >> 1;
    const int n0   = blockIdx.x * 128;
    const int m0   = blockIdx.y * 128;

    const __half* A  = (MODE == 0) ? g_Xh : g_Zh;
    const __half* Bw = (MODE == 0) ? g_Wth : (g_Wth + (size_t)3072 * 1024);

    const __half* srcA[4];
    const __half* srcB[4];
    uint32_t dstOff[4];
    #pragma unroll
    for (int i = 0; i < 4; i++) {
        int idx = i * 256 + tid;
        int row = idx >> 3;
        int c8  = idx & 7;
        srcA[i] = A  + (size_t)(m0 + row) * 1024 + c8 * 8;
        srcB[i] = Bw + (size_t)(n0 + row) * 1024 + c8 * 8;
        dstOff[i] = (uint32_t)(row * HStr + c8 * 8) * 2;
    }

    const int laneRowA = ((lane >> 3) & 1) * 8 + (lane & 7);
    const int laneColA = (lane >> 4) * 8;
    uint32_t aLane[4];
    #pragma unroll
    for (int mt = 0; mt < 4; mt++)
        aLane[mt] = (uint32_t)((wm * 64 + mt * 16 + laneRowA) * HStr + laneColA) * 2;
    uint32_t bPair[2];
    #pragma unroll
    for (int np = 0; np < 2; np++)
        bPair[np] = (uint32_t)((wn * 32 + np * 16 + (lane >> 4) * 8 + (lane & 7)) * HStr
                               + ((lane >> 3) & 1) * 8) * 2;

    float acc[4][4][4];
    #pragma unroll
    for (int mt = 0; mt < 4; mt++)
        #pragma unroll
        for (int nt = 0; nt < 4; nt++)
            #pragma unroll
            for (int e = 0; e < 4; e++) acc[mt][nt][e] = 0.f;

    #pragma unroll
    for (int st = 0; st < 2; st++) {
        uint32_t base = s0 + st * GEMM_STAGE_B;
        int kt = st * 64;
        #pragma unroll
        for (int i = 0; i < 4; i++) {
            cp16(base + dstOff[i], srcA[i] + kt);
            cp16(base + bHalfOff + dstOff[i], srcB[i] + kt);
        }
        cp_commit();
    }

    const int mrot = (wid >> 1) & 3;   // second desync axis (per n-warp)
    int stC = 0;
    for (int ch = 0; ch < 16; ch++) {
        if (ch < 15) cp_wait<1>(); else cp_wait<0>();
        __syncthreads();

        int stN = stC + 2; if (stN >= 3) stN -= 3;
        const uint32_t pfBase = s0 + stN * GEMM_STAGE_B;
        const int pfKt = (ch + 2) * 64;
        const bool doPf = (ch < 14);

        const uint32_t sAs = s0 + stC * GEMM_STAGE_B;
        const uint32_t sBs = sAs + bHalfOff;

        #pragma unroll
        for (int ksi = 0; ksi < 4; ksi++) {
            const int ks = (ksi + wid) & 3;   // per-warp rotation: desync LDSM bursts
            if (doPf) {
                cp16(pfBase + dstOff[ksi], srcA[ksi] + pfKt);
                cp16(pfBase + bHalfOff + dstOff[ksi], srcB[ksi] + pfKt);
            }
            const uint32_t kOff = (uint32_t)(ks * 16) * 2;
            uint32_t bf[4][2];
            #pragma unroll
            for (int np = 0; np < 2; np++) {
                uint32_t q[4];
                ldsm_x4(q, sBs + bPair[np] + kOff);
                bf[2 * np][0] = q[0];     bf[2 * np][1] = q[1];
                bf[2 * np + 1][0] = q[2]; bf[2 * np + 1][1] = q[3];
            }
            #pragma unroll
            for (int mt = 0; mt < 4; mt++) {
                const int mtr = (mt + mrot) & 3;
                uint32_t af[4];
                ldsm_x4(af, sAs + aLane[mtr] + kOff);
                #pragma unroll
                for (int nt = 0; nt < 4; nt++)
                    mma_f16(acc[mtr][nt], af, bf[nt]);
            }
        }
        if (doPf) cp_commit();
        if (++stC >= 3) stC = 0;
    }

    // Epilogue
    #pragma unroll
    for (int nt = 0; nt < 4; nt++) {
        int n_base = n0 + wn * 32 + nt * 8;
        int ncol   = 2 * tig;
        if (MODE == 0) {
            int sel = n_base >> 10;
            int hh  = (n_base >> 6) & 15;
            int kk  = (n_base & 63) + ncol;
            const float* bias = (sel == 0) ? b0 : (sel == 1) ? b1 : b2;
            __half* dst = (sel == 0) ? g_Qh : (sel == 1) ? g_Kh : g_Vh;
            float scale = (sel == 0) ? 0.18033688f : 1.0f;   // 0.125*log2(e)
            float bv0 = bias[hh * 64 + kk];
            float bv1 = bias[hh * 64 + kk + 1];
            #pragma unroll
            for (int mt = 0; mt < 4; mt++) {
                int r = m0 + wm * 64 + mt * 16 + grp;
                #pragma unroll
                for (int hrow = 0; hrow < 2; hrow++) {
                    int m  = r + hrow * 8;
                    int bb = m >> 10, ss = m & 1023;
                    float v0 = (acc[mt][nt][hrow * 2 + 0] + bv0) * scale;
                    float v1 = (acc[mt][nt][hrow * 2 + 1] + bv1) * scale;
                    *reinterpret_cast<__half2*>(
                        &dst[((size_t)(bb * 16 + hh) * 1024 + ss) * 64 + kk]) =
                        __floats2half2_rn(v0, v1);
                }
            }
        } else {
            int n  = n_base + ncol;
            float bv0 = b0[n], bv1 = b0[n + 1];
            #pragma unroll
            for (int mt = 0; mt < 4; mt++) {
                int r = m0 + wm * 64 + mt * 16 + grp;
                #pragma unroll
                for (int hrow = 0; hrow < 2; hrow++) {
                    int m = r + hrow * 8;
                    float2 xr = *reinterpret_cast<const float2*>(
                        &Xres[(size_t)m * 1024 + n]);
                    float2 v;
                    v.x = acc[mt][nt][hrow * 2 + 0] + bv0 + xr.x;
                    v.y = acc[mt][nt][hrow * 2 + 1] + bv1 + xr.y;
                    *reinterpret_cast<float2*>(&Out[(size_t)m * 1024 + n]) = v;
                }
            }
        }
    }
}

// ---------------------------------------------------------------------------
// Kernel 2: flash attention. fp16 mma, exp2 softmax, register-resident P,
// paired ldmatrix.x4. NEW: per-warp kk rotation in both MMA loops + next-tile
// cp.async spread through the S loop.
// ---------------------------------------------------------------------------
#define ATTN_SMEM ((128 + 2 * 64 + 2 * 64) * HStr * 2)

__global__ __launch_bounds__(256, 2) void attn_mma_kernel()
{
    extern __shared__ __half smh[];
    __half* Ps    = smh;                       // 128 x 72 (Q staging only)
    __half* KsBuf = smh + 128 * HStr;          // 2 x 64 x 72
    __half* VsBuf = KsBuf + 2 * 64 * HStr;     // 2 x 64 x 72
    const uint32_t sPs = smem_u32(Ps);
    const uint32_t sK0 = smem_u32(KsBuf);
    const uint32_t sV0 = smem_u32(VsBuf);
    const uint32_t tileBytes = 64 * HStr * 2;

    const int q0 = blockIdx.x * 128;
    const int h  = blockIdx.y;
    const int b  = blockIdx.z;
    const int bh = b * Hn + h;

    const __half* Qg = g_Qh + (size_t)bh * Sn * DKn;
    const __half* Kg = g_Kh + (size_t)bh * Sn * DKn;
    const __half* Vg = g_Vh + (size_t)bh * Sn * DKn;

    const int tid  = threadIdx.x;
    const int wid  = tid >> 5;
    const int lane = tid & 31;
    const int r0   = wid * 16;

    const int laneRowA = ((lane >> 3) & 1) * 8 + (lane & 7);
    const int laneColA = (lane >> 4) * 8;
    const uint32_t pLane = (uint32_t)((r0 + laneRowA) * HStr + laneColA) * 2;
    uint32_t kPair[4];
    #pragma unroll
    for (int np = 0; np < 4; np++)
        kPair[np] = (uint32_t)((np * 16 + (lane >> 4) * 8 + (lane & 7)) * HStr
                               + ((lane >> 3) & 1) * 8) * 2;
    uint32_t vPair[4];
    #pragma unroll
    for (int np = 0; np < 4; np++)
        vPair[np] = (uint32_t)((((lane >> 3) & 1) * 8 + (lane & 7)) * HStr
                               + np * 16 + (lane >> 4) * 8) * 2;

    const __half* srcK[2];
    const __half* srcV[2];
    uint32_t dstKV[2];
    #pragma unroll
    for (int i = 0; i < 2; i++) {
        int idx = i * 256 + tid;
        int row = idx >> 3;
        int c8  = idx & 7;
        srcK[i] = Kg + (size_t)row * DKn + c8 * 8;
        srcV[i] = Vg + (size_t)row * DKn + c8 * 8;
        dstKV[i] = (uint32_t)(row * HStr + c8 * 8) * 2;
    }
    const __half* srcQ[4];
    uint32_t dstQ[4];
    #pragma unroll
    for (int i = 0; i < 4; i++) {
        int idx = i * 256 + tid;
        int row = idx >> 3;
        int c8  = idx & 7;
        srcQ[i] = Qg + (size_t)(q0 + row) * DKn + c8 * 8;
        dstQ[i] = (uint32_t)(row * HStr + c8 * 8) * 2;
    }

    // Prologue: stage K/V tile 0 and Q
    #pragma unroll
    for (int i = 0; i < 2; i++) {
        cp16(sK0 + dstKV[i], srcK[i]);
        cp16(sV0 + dstKV[i], srcV[i]);
    }
    #pragma unroll
    for (int i = 0; i < 4; i++) cp16(sPs + dstQ[i], srcQ[i]);
    cp_commit();
    cp_wait<0>();
    __syncthreads();

    uint32_t qf[4][4];
    #pragma unroll
    for (int kk = 0; kk < 4; kk++)
        ldsm_x4(qf[kk], sPs + pLane + (uint32_t)(kk * 16) * 2);

    float m_i[2] = {-3.0e38f, -3.0e38f};
    float l_i[2] = {0.f, 0.f};
    float o[8][4];
    #pragma unroll
    for (int nt = 0; nt < 8; nt++)
        #pragma unroll
        for (int e = 0; e < 4; e++) o[nt][e] = 0.f;

    const int krot = wid & 3;
    for (int ti = 0; ti < 16; ti++) {
        cp_wait<0>();
        __syncthreads();

        const bool doPf = (ti < 15);
        const int pfOff = (ti + 1) * 64 * DKn;
        const uint32_t pfBoff = ((ti + 1) & 1) * tileBytes;

        const uint32_t sKs = sK0 + (ti & 1) * tileBytes;
        const uint32_t sVs = sV0 + (ti & 1) * tileBytes;

        // S = Q K^T — per-warp kk rotation; next-tile cp16 spread across steps
        float s[8][4];
        #pragma unroll
        for (int nt = 0; nt < 8; nt++)
            #pragma unroll
            for (int e = 0; e < 4; e++) s[nt][e] = 0.f;

        #pragma unroll
        for (int kki = 0; kki < 4; kki++) {
            const int kk = (kki + krot) & 3;
            if (doPf && kki < 2) {
                cp16(sK0 + pfBoff + dstKV[kki], srcK[kki] + pfOff);
                cp16(sV0 + pfBoff + dstKV[kki], srcV[kki] + pfOff);
            }
            const uint32_t kOff = (uint32_t)(kk * 16) * 2;
            #pragma unroll
            for (int np = 0; np < 4; np++) {
                uint32_t q[4];
                ldsm_x4(q, sKs + kPair[np] + kOff);
                mma_f16(s[2 * np],     qf[kk], q);
                mma_f16(s[2 * np + 1], qf[kk], q + 2);
            }
        }
        if (doPf) cp_commit();

        // Online softmax in exp2 domain
        float rm0 = -3.0e38f, rm1 = -3.0e38f;
        #pragma unroll
        for (int nt = 0; nt < 8; nt++) {
            rm0 = fmaxf(rm0, fmaxf(s[nt][0], s[nt][1]));
            rm1 = fmaxf(rm1, fmaxf(s[nt][2], s[nt][3]));
        }
        rm0 = fmaxf(rm0, __shfl_xor_sync(0xffffffffu, rm0, 1));
        rm0 = fmaxf(rm0, __shfl_xor_sync(0xffffffffu, rm0, 2));
        rm1 = fmaxf(rm1, __shfl_xor_sync(0xffffffffu, rm1, 1));
        rm1 = fmaxf(rm1, __shfl_xor_sync(0xffffffffu, rm1, 2));

        float nm0 = fmaxf(m_i[0], rm0);
        float nm1 = fmaxf(m_i[1], rm1);
        float corr0 = ex2f(m_i[0] - nm0);
        float corr1 = ex2f(m_i[1] - nm1);
        m_i[0] = nm0; m_i[1] = nm1;

        float rs0 = 0.f, rs1 = 0.f;
        #pragma unroll
        for (int nt = 0; nt < 8; nt++) {
            s[nt][0] = ex2f(s[nt][0] - nm0);
            s[nt][1] = ex2f(s[nt][1] - nm0);
            s[nt][2] = ex2f(s[nt][2] - nm1);
            s[nt][3] = ex2f(s[nt][3] - nm1);
            rs0 += s[nt][0] + s[nt][1];
            rs1 += s[nt][2] + s[nt][3];
        }
        rs0 += __shfl_xor_sync(0xffffffffu, rs0, 1);
        rs0 += __shfl_xor_sync(0xffffffffu, rs0, 2);
        rs1 += __shfl_xor_sync(0xffffffffu, rs1, 1);
        rs1 += __shfl_xor_sync(0xffffffffu, rs1, 2);
        l_i[0] = l_i[0] * corr0 + rs0;
        l_i[1] = l_i[1] * corr1 + rs1;

        #pragma unroll
        for (int nt = 0; nt < 8; nt++) {
            o[nt][0] *= corr0; o[nt][1] *= corr0;
            o[nt][2] *= corr1; o[nt][3] *= corr1;
        }

        // O += P V — per-warp kk rotation (all P fragments already computed).
        #pragma unroll
        for (int kki = 0; kki < 4; kki++) {
            const int kk = (kki + krot) & 3;
            __half2 a0 = __floats2half2_rn(s[2 * kk][0],     s[2 * kk][1]);
            __half2 a1 = __floats2half2_rn(s[2 * kk][2],     s[2 * kk][3]);
            __half2 a2 = __floats2half2_rn(s[2 * kk + 1][0], s[2 * kk + 1][1]);
            __half2 a3 = __floats2half2_rn(s[2 * kk + 1][2], s[2 * kk + 1][3]);
            uint32_t af[4];
            af[0] = *reinterpret_cast<uint32_t*>(&a0);
            af[1] = *reinterpret_cast<uint32_t*>(&a1);
            af[2] = *reinterpret_cast<uint32_t*>(&a2);
            af[3] = *reinterpret_cast<uint32_t*>(&a3);
            const uint32_t vBase = sVs + (uint32_t)(kk * 16 * HStr) * 2;
            #pragma unroll
            for (int np = 0; np < 4; np++) {
                uint32_t q[4];
                ldsm_x4t(q, vBase + vPair[np]);
                mma_f16(o[2 * np],     af, q);
                mma_f16(o[2 * np + 1], af, q + 2);
            }
        }
    }

    // Epilogue: normalize, write half to concat layout g_Zh[b, s, h*64+dv]
    const int grp = lane >> 2;
    const int tig = lane & 3;
    float inv0 = 1.0f / l_i[0];
    float inv1 = 1.0f / l_i[1];
    int row0 = q0 + r0 + grp;
    #pragma unroll
    for (int nt = 0; nt < 8; nt++) {
        int col = h * 64 + nt * 8 + 2 * tig;
        *reinterpret_cast<__half2*>(
            &g_Zh[((size_t)b * Sn + row0) * 1024 + col]) =
            __floats2half2_rn(o[nt][0] * inv0, o[nt][1] * inv0);
        *reinterpret_cast<__half2*>(
            &g_Zh[((size_t)b * Sn + row0 + 8) * 1024 + col]) =
            __floats2half2_rn(o[nt][2] * inv1, o[nt][3] * inv1);
    }
}

// ---------------------------------------------------------------------------
extern "C" void kernel_launch(void* const* d_in, const int* in_sizes, int n_in,
                              void* d_out, int out_size)
{
    const float* X  = (const float*)d_in[0];
    const float* Wk = (const float*)d_in[1];
    const float* bk = (const float*)d_in[2];
    const float* Wq = (const float*)d_in[3];
    const float* bq = (const float*)d_in[4];
    const float* Wv = (const float*)d_in[5];
    const float* bv = (const float*)d_in[6];
    const float* Wo = (const float*)d_in[7];
    const float* bo = (const float*)d_in[8];
    float* out = (float*)d_out;

    cudaFuncSetAttribute(gemm_mma_kernel<0>,
                         cudaFuncAttributeMaxDynamicSharedMemorySize, GEMM_SMEM);
    cudaFuncSetAttribute(gemm_mma_kernel<1>,
                         cudaFuncAttributeMaxDynamicSharedMemorySize, GEMM_SMEM);
    cudaFuncSetAttribute(attn_mma_kernel,
                         cudaFuncAttributeMaxDynamicSharedMemorySize, ATTN_SMEM);

    prep_kernel<<<5120, 256>>>(X, Wq, Wk, Wv, Wo);
    gemm_mma_kernel<0><<<dim3(24, 32), 256, GEMM_SMEM>>>(
        bq, bk, bv, nullptr, nullptr);
    attn_mma_kernel<<<dim3(Sn / 128, Hn, Bn), 256, ATTN_SMEM>>>();
    gemm_mma_kernel<1><<<dim3(8, 32), 256, GEMM_SMEM>>>(
        bo, nullptr, nullptr, X, out);
}

// round 17
// speedup vs baseline: 4.9577x; 4.9577x over previous
#include <cuda_runtime.h>
#include <cuda_fp16.h>
#include <cstdint>

#define Bn  4
#define Sn  1024
#define DMn 1024
#define Hn  16
#define DKn 64

// Scratch (allocation-free rule: __device__ globals). All half.
__device__ __half g_Xh[(size_t)Bn * Sn * DMn];        // X in half
__device__ __half g_Qh[(size_t)Bn * Hn * Sn * DKn];   // pre-scaled by 0.125*log2e
__device__ __half g_Kh[(size_t)Bn * Hn * Sn * DKn];
__device__ __half g_Vh[(size_t)Bn * Hn * Sn * DKn];
__device__ __half g_Zh[(size_t)Bn * Sn * Hn * DKn];   // [b,s,h*64+v]
// K-major half weights: rows n, cols d.
//   n in [0,1024): Q | [1024,2048): K | [2048,3072): V | [3072,4096): Wo col
__device__ __half g_Wth[(size_t)4096 * 1024];

__device__ __forceinline__ uint32_t smem_u32(const void* p) {
    uint32_t a;
    asm("{ .reg .u64 t; cvta.to.shared.u64 t, %1; cvt.u32.u64 %0, t; }"
        : "=r"(a) : "l"(p));
    return a;
}
__device__ __forceinline__ void cp16(uint32_t dst, const void* src) {
    asm volatile("cp.async.cg.shared.global [%0], [%1], 16;"
                 :: "r"(dst), "l"(src));
}
__device__ __forceinline__ void cp_commit() {
    asm volatile("cp.async.commit_group;");
}
template <int N>
__device__ __forceinline__ void cp_wait() {
    asm volatile("cp.async.wait_group %0;" :: "n"(N));
}
__device__ __forceinline__ void ldsm_x4(uint32_t* r, uint32_t addr) {
    asm volatile("ldmatrix.sync.aligned.m8n8.x4.shared.b16 {%0,%1,%2,%3}, [%4];"
                 : "=r"(r[0]), "=r"(r[1]), "=r"(r[2]), "=r"(r[3]) : "r"(addr));
}
__device__ __forceinline__ void ldsm_x4t(uint32_t* r, uint32_t addr) {
    asm volatile("ldmatrix.sync.aligned.m8n8.x4.trans.shared.b16 {%0,%1,%2,%3}, [%4];"
                 : "=r"(r[0]), "=r"(r[1]), "=r"(r[2]), "=r"(r[3]) : "r"(addr));
}
__device__ __forceinline__ float ex2f(float x) {
    float y;
    asm("ex2.approx.f32 %0, %1;" : "=f"(y) : "f"(x));
    return y;
}

// fp16 mma: m16n8k16, f32 accumulate.
__device__ __forceinline__ void mma_f16(float* c, const uint32_t* a, const uint32_t* b) {
    asm volatile(
        "mma.sync.aligned.m16n8k16.row.col.f32.f16.f16.f32 "
        "{%0,%1,%2,%3}, {%4,%5,%6,%7}, {%8,%9}, {%0,%1,%2,%3};"
        : "+f"(c[0]), "+f"(c[1]), "+f"(c[2]), "+f"(c[3])
        : "r"(a[0]), "r"(a[1]), "r"(a[2]), "r"(a[3]), "r"(b[0]), "r"(b[1]));
}

// ---------------------------------------------------------------------------
// Kernel 0 (fused prep): blocks [0,1024) convert X->half (16 elems/thread);
// blocks [1024,5120) transpose weights to K-major half.
// ---------------------------------------------------------------------------
__global__ __launch_bounds__(256) void prep_kernel(
    const float* __restrict__ X,
    const float* __restrict__ Wq, const float* __restrict__ Wk,
    const float* __restrict__ Wv, const float* __restrict__ Wo)
{
    int blk = blockIdx.x;
    int tid = threadIdx.x;
    if (blk < 1024) {
        size_t base = ((size_t)blk * 256 + tid) * 16;
        #pragma unroll
        for (int j = 0; j < 4; j++) {
            float4 v = *reinterpret_cast<const float4*>(&X[base + j * 4]);
            __half2 h0 = __floats2half2_rn(v.x, v.y);
            __half2 h1 = __floats2half2_rn(v.z, v.w);
            uint2 pk;
            pk.x = *reinterpret_cast<uint32_t*>(&h0);
            pk.y = *reinterpret_cast<uint32_t*>(&h1);
            *reinterpret_cast<uint2*>(&g_Xh[base + j * 4]) = pk;
        }
        return;
    }
    __shared__ float t[32][33];
    int bid = blk - 1024;
    int bx  = bid & 127;
    int by  = bid >> 7;
    int n0 = bx * 32;
    int d0 = by * 32;
    int r  = n0 >> 10;

    #pragma unroll
    for (int p = 0; p < 4; p++) {
        int idx = p * 256 + tid;
        int dl  = idx >> 5;
        int j   = idx & 31;
        int d   = d0 + dl;
        float v;
        if (r < 3) {
            int hh = (n0 >> 6) & 15;
            int k0 = n0 & 63;
            const float* W = (r == 0) ? Wq : (r == 1) ? Wk : Wv;
            v = W[(size_t)hh * 65536 + (size_t)d * 64 + k0 + j];
        } else {
            v = Wo[(size_t)d * 1024 + (n0 - 3072) + j];
        }
        t[dl][j] = v;
    }
    __syncthreads();
    #pragma unroll
    for (int p = 0; p < 4; p++) {
        int idx = p * 256 + tid;
        int nl  = idx >> 5;
        int dd  = idx & 31;
        g_Wth[(size_t)(n0 + nl) * 1024 + d0 + dd] = __float2half_rn(t[dd][nl]);
    }
}

// ---------------------------------------------------------------------------
// fp16 mma GEMM (R15 champion): BM=128, BN=128, 8 warps (2m x 4n), K-chunk=64,
// 16 chunks, 3-stage cp.async ring, 2 CTAs/SM. Per-warp ks rotation (addresses
// ONLY — register arrays indexed statically), cp.async spread across ks steps.
// ---------------------------------------------------------------------------
#define HStr 72
#define GEMM_STAGE_B ((128 + 128) * HStr * 2)
#define GEMM_SMEM    (3 * GEMM_STAGE_B)

template <int MODE>
__global__ __launch_bounds__(256, 2) void gemm_mma_kernel(
    const float* __restrict__ b0, const float* __restrict__ b1,
    const float* __restrict__ b2,
    const float* __restrict__ Xres, float* __restrict__ Out)
{
    extern __shared__ __half smh[];
    const uint32_t s0 = smem_u32(smh);
    const uint32_t bHalfOff = 128 * HStr * 2;

    const int tid  = threadIdx.x;
    const int wid  = tid >> 5;
    const int lane = tid & 31;
    const int grp  = lane >> 2;
    const int tig  = lane & 3;
    const int wm   = wid & 1;
    const int wn   = wid >> 1;
    const int n0   = blockIdx.x * 128;
    const int m0   = blockIdx.y * 128;

    const __half* A  = (MODE == 0) ? g_Xh : g_Zh;
    const __half* Bw = (MODE == 0) ? g_Wth : (g_Wth + (size_t)3072 * 1024);

    const __half* srcA[4];
    const __half* srcB[4];
    uint32_t dstOff[4];
    #pragma unroll
    for (int i = 0; i < 4; i++) {
        int idx = i * 256 + tid;
        int row = idx >> 3;
        int c8  = idx & 7;
        srcA[i] = A  + (size_t)(m0 + row) * 1024 + c8 * 8;
        srcB[i] = Bw + (size_t)(n0 + row) * 1024 + c8 * 8;
        dstOff[i] = (uint32_t)(row * HStr + c8 * 8) * 2;
    }

    const int laneRowA = ((lane >> 3) & 1) * 8 + (lane & 7);
    const int laneColA = (lane >> 4) * 8;
    uint32_t aLane[4];
    #pragma unroll
    for (int mt = 0; mt < 4; mt++)
        aLane[mt] = (uint32_t)((wm * 64 + mt * 16 + laneRowA) * HStr + laneColA) * 2;
    uint32_t bPair[2];
    #pragma unroll
    for (int np = 0; np < 2; np++)
        bPair[np] = (uint32_t)((wn * 32 + np * 16 + (lane >> 4) * 8 + (lane & 7)) * HStr
                               + ((lane >> 3) & 1) * 8) * 2;

    float acc[4][4][4];
    #pragma unroll
    for (int mt = 0; mt < 4; mt++)
        #pragma unroll
        for (int nt = 0; nt < 4; nt++)
            #pragma unroll
            for (int e = 0; e < 4; e++) acc[mt][nt][e] = 0.f;

    #pragma unroll
    for (int st = 0; st < 2; st++) {
        uint32_t base = s0 + st * GEMM_STAGE_B;
        int kt = st * 64;
        #pragma unroll
        for (int i = 0; i < 4; i++) {
            cp16(base + dstOff[i], srcA[i] + kt);
            cp16(base + bHalfOff + dstOff[i], srcB[i] + kt);
        }
        cp_commit();
    }

    int stC = 0;
    for (int ch = 0; ch < 16; ch++) {
        if (ch < 15) cp_wait<1>(); else cp_wait<0>();
        __syncthreads();

        int stN = stC + 2; if (stN >= 3) stN -= 3;
        const uint32_t pfBase = s0 + stN * GEMM_STAGE_B;
        const int pfKt = (ch + 2) * 64;
        const bool doPf = (ch < 14);

        const uint32_t sAs = s0 + stC * GEMM_STAGE_B;
        const uint32_t sBs = sAs + bHalfOff;

        #pragma unroll
        for (int ksi = 0; ksi < 4; ksi++) {
            const int ks = (ksi + wid) & 3;   // address-only rotation (safe)
            if (doPf) {
                cp16(pfBase + dstOff[ksi], srcA[ksi] + pfKt);
                cp16(pfBase + bHalfOff + dstOff[ksi], srcB[ksi] + pfKt);
            }
            const uint32_t kOff = (uint32_t)(ks * 16) * 2;
            uint32_t bf[4][2];
            #pragma unroll
            for (int np = 0; np < 2; np++) {
                uint32_t q[4];
                ldsm_x4(q, sBs + bPair[np] + kOff);
                bf[2 * np][0] = q[0];     bf[2 * np][1] = q[1];
                bf[2 * np + 1][0] = q[2]; bf[2 * np + 1][1] = q[3];
            }
            #pragma unroll
            for (int mt = 0; mt < 4; mt++) {
                uint32_t af[4];
                ldsm_x4(af, sAs + aLane[mt] + kOff);
                #pragma unroll
                for (int nt = 0; nt < 4; nt++)
                    mma_f16(acc[mt][nt], af, bf[nt]);
            }
        }
        if (doPf) cp_commit();
        if (++stC >= 3) stC = 0;
    }

    // Epilogue
    #pragma unroll
    for (int nt = 0; nt < 4; nt++) {
        int n_base = n0 + wn * 32 + nt * 8;
        int ncol   = 2 * tig;
        if (MODE == 0) {
            int sel = n_base >> 10;
            int hh  = (n_base >> 6) & 15;
            int kk  = (n_base & 63) + ncol;
            const float* bias = (sel == 0) ? b0 : (sel == 1) ? b1 : b2;
            __half* dst = (sel == 0) ? g_Qh : (sel == 1) ? g_Kh : g_Vh;
            float scale = (sel == 0) ? 0.18033688f : 1.0f;   // 0.125*log2(e)
            float bv0 = bias[hh * 64 + kk];
            float bv1 = bias[hh * 64 + kk + 1];
            #pragma unroll
            for (int mt = 0; mt < 4; mt++) {
                int r = m0 + wm * 64 + mt * 16 + grp;
                #pragma unroll
                for (int hrow = 0; hrow < 2; hrow++) {
                    int m  = r + hrow * 8;
                    int bb = m >> 10, ss = m & 1023;
                    float v0 = (acc[mt][nt][hrow * 2 + 0] + bv0) * scale;
                    float v1 = (acc[mt][nt][hrow * 2 + 1] + bv1) * scale;
                    *reinterpret_cast<__half2*>(
                        &dst[((size_t)(bb * 16 + hh) * 1024 + ss) * 64 + kk]) =
                        __floats2half2_rn(v0, v1);
                }
            }
        } else {
            int n  = n_base + ncol;
            float bv0 = b0[n], bv1 = b0[n + 1];
            #pragma unroll
            for (int mt = 0; mt < 4; mt++) {
                int r = m0 + wm * 64 + mt * 16 + grp;
                #pragma unroll
                for (int hrow = 0; hrow < 2; hrow++) {
                    int m = r + hrow * 8;
                    float2 xr = *reinterpret_cast<const float2*>(
                        &Xres[(size_t)m * 1024 + n]);
                    float2 v;
                    v.x = acc[mt][nt][hrow * 2 + 0] + bv0 + xr.x;
                    v.y = acc[mt][nt][hrow * 2 + 1] + bv1 + xr.y;
                    *reinterpret_cast<float2*>(&Out[(size_t)m * 1024 + n]) = v;
                }
            }
        }
    }
}

// ---------------------------------------------------------------------------
// Kernel 2: flash attention (R12/R15 form). fp16 mma, exp2 softmax,
// register-resident P, paired ldmatrix.x4. NO rotations (register-array safe);
// next-tile cp16s spread across S-loop steps (static indices only).
// ---------------------------------------------------------------------------
#define ATTN_SMEM ((128 + 2 * 64 + 2 * 64) * HStr * 2)

__global__ __launch_bounds__(256, 2) void attn_mma_kernel()
{
    extern __shared__ __half smh[];
    __half* Ps    = smh;                       // 128 x 72 (Q staging only)
    __half* KsBuf = smh + 128 * HStr;          // 2 x 64 x 72
    __half* VsBuf = KsBuf + 2 * 64 * HStr;     // 2 x 64 x 72
    const uint32_t sPs = smem_u32(Ps);
    const uint32_t sK0 = smem_u32(KsBuf);
    const uint32_t sV0 = smem_u32(VsBuf);
    const uint32_t tileBytes = 64 * HStr * 2;

    const int q0 = blockIdx.x * 128;
    const int h  = blockIdx.y;
    const int b  = blockIdx.z;
    const int bh = b * Hn + h;

    const __half* Qg = g_Qh + (size_t)bh * Sn * DKn;
    const __half* Kg = g_Kh + (size_t)bh * Sn * DKn;
    const __half* Vg = g_Vh + (size_t)bh * Sn * DKn;

    const int tid  = threadIdx.x;
    const int wid  = tid >> 5;
    const int lane = tid & 31;
    const int r0   = wid * 16;

    const int laneRowA = ((lane >> 3) & 1) * 8 + (lane & 7);
    const int laneColA = (lane >> 4) * 8;
    const uint32_t pLane = (uint32_t)((r0 + laneRowA) * HStr + laneColA) * 2;
    uint32_t kPair[4];
    #pragma unroll
    for (int np = 0; np < 4; np++)
        kPair[np] = (uint32_t)((np * 16 + (lane >> 4) * 8 + (lane & 7)) * HStr
                               + ((lane >> 3) & 1) * 8) * 2;
    uint32_t vPair[4];
    #pragma unroll
    for (int np = 0; np < 4; np++)
        vPair[np] = (uint32_t)((((lane >> 3) & 1) * 8 + (lane & 7)) * HStr
                               + np * 16 + (lane >> 4) * 8) * 2;

    const __half* srcK[2];
    const __half* srcV[2];
    uint32_t dstKV[2];
    #pragma unroll
    for (int i = 0; i < 2; i++) {
        int idx = i * 256 + tid;
        int row = idx >> 3;
        int c8  = idx & 7;
        srcK[i] = Kg + (size_t)row * DKn + c8 * 8;
        srcV[i] = Vg + (size_t)row * DKn + c8 * 8;
        dstKV[i] = (uint32_t)(row * HStr + c8 * 8) * 2;
    }
    const __half* srcQ[4];
    uint32_t dstQ[4];
    #pragma unroll
    for (int i = 0; i < 4; i++) {
        int idx = i * 256 + tid;
        int row = idx >> 3;
        int c8  = idx & 7;
        srcQ[i] = Qg + (size_t)(q0 + row) * DKn + c8 * 8;
        dstQ[i] = (uint32_t)(row * HStr + c8 * 8) * 2;
    }

    // Prologue: stage K/V tile 0 and Q
    #pragma unroll
    for (int i = 0; i < 2; i++) {
        cp16(sK0 + dstKV[i], srcK[i]);
        cp16(sV0 + dstKV[i], srcV[i]);
    }
    #pragma unroll
    for (int i = 0; i < 4; i++) cp16(sPs + dstQ[i], srcQ[i]);
    cp_commit();
    cp_wait<0>();
    __syncthreads();

    uint32_t qf[4][4];
    #pragma unroll
    for (int kk = 0; kk < 4; kk++)
        ldsm_x4(qf[kk], sPs + pLane + (uint32_t)(kk * 16) * 2);

    float m_i[2] = {-3.0e38f, -3.0e38f};
    float l_i[2] = {0.f, 0.f};
    float o[8][4];
    #pragma unroll
    for (int nt = 0; nt < 8; nt++)
        #pragma unroll
        for (int e = 0; e < 4; e++) o[nt][e] = 0.f;

    for (int ti = 0; ti < 16; ti++) {
        cp_wait<0>();
        __syncthreads();

        const bool doPf = (ti < 15);
        const int pfOff = (ti + 1) * 64 * DKn;
        const uint32_t pfBoff = ((ti + 1) & 1) * tileBytes;

        const uint32_t sKs = sK0 + (ti & 1) * tileBytes;
        const uint32_t sVs = sV0 + (ti & 1) * tileBytes;

        // S = Q K^T — next-tile cp16s spread across first two kk steps
        float s[8][4];
        #pragma unroll
        for (int nt = 0; nt < 8; nt++)
            #pragma unroll
            for (int e = 0; e < 4; e++) s[nt][e] = 0.f;

        #pragma unroll
        for (int kk = 0; kk < 4; kk++) {
            if (doPf && kk < 2) {
                cp16(sK0 + pfBoff + dstKV[kk], srcK[kk] + pfOff);
                cp16(sV0 + pfBoff + dstKV[kk], srcV[kk] + pfOff);
            }
            const uint32_t kOff = (uint32_t)(kk * 16) * 2;
            #pragma unroll
            for (int np = 0; np < 4; np++) {
                uint32_t q[4];
                ldsm_x4(q, sKs + kPair[np] + kOff);
                mma_f16(s[2 * np],     qf[kk], q);
                mma_f16(s[2 * np + 1], qf[kk], q + 2);
            }
        }
        if (doPf) cp_commit();

        // Online softmax in exp2 domain
        float rm0 = -3.0e38f, rm1 = -3.0e38f;
        #pragma unroll
        for (int nt = 0; nt < 8; nt++) {
            rm0 = fmaxf(rm0, fmaxf(s[nt][0], s[nt][1]));
            rm1 = fmaxf(rm1, fmaxf(s[nt][2], s[nt][3]));
        }
        rm0 = fmaxf(rm0, __shfl_xor_sync(0xffffffffu, rm0, 1));
        rm0 = fmaxf(rm0, __shfl_xor_sync(0xffffffffu, rm0, 2));
        rm1 = fmaxf(rm1, __shfl_xor_sync(0xffffffffu, rm1, 1));
        rm1 = fmaxf(rm1, __shfl_xor_sync(0xffffffffu, rm1, 2));

        float nm0 = fmaxf(m_i[0], rm0);
        float nm1 = fmaxf(m_i[1], rm1);
        float corr0 = ex2f(m_i[0] - nm0);
        float corr1 = ex2f(m_i[1] - nm1);
        m_i[0] = nm0; m_i[1] = nm1;

        float rs0 = 0.f, rs1 = 0.f;
        #pragma unroll
        for (int nt = 0; nt < 8; nt++) {
            s[nt][0] = ex2f(s[nt][0] - nm0);
            s[nt][1] = ex2f(s[nt][1] - nm0);
            s[nt][2] = ex2f(s[nt][2] - nm1);
            s[nt][3] = ex2f(s[nt][3] - nm1);
            rs0 += s[nt][0] + s[nt][1];
            rs1 += s[nt][2] + s[nt][3];
        }
        rs0 += __shfl_xor_sync(0xffffffffu, rs0, 1);
        rs0 += __shfl_xor_sync(0xffffffffu, rs0, 2);
        rs1 += __shfl_xor_sync(0xffffffffu, rs1, 1);
        rs1 += __shfl_xor_sync(0xffffffffu, rs1, 2);
        l_i[0] = l_i[0] * corr0 + rs0;
        l_i[1] = l_i[1] * corr1 + rs1;

        #pragma unroll
        for (int nt = 0; nt < 8; nt++) {
            o[nt][0] *= corr0; o[nt][1] *= corr0;
            o[nt][2] *= corr1; o[nt][3] *= corr1;
        }

        // O += P V. P's C-fragment layout IS the A-fragment layout (registers).
        #pragma unroll
        for (int kk = 0; kk < 4; kk++) {
            __half2 a0 = __floats2half2_rn(s[2 * kk][0],     s[2 * kk][1]);
            __half2 a1 = __floats2half2_rn(s[2 * kk][2],     s[2 * kk][3]);
            __half2 a2 = __floats2half2_rn(s[2 * kk + 1][0], s[2 * kk + 1][1]);
            __half2 a3 = __floats2half2_rn(s[2 * kk + 1][2], s[2 * kk + 1][3]);
            uint32_t af[4];
            af[0] = *reinterpret_cast<uint32_t*>(&a0);
            af[1] = *reinterpret_cast<uint32_t*>(&a1);
            af[2] = *reinterpret_cast<uint32_t*>(&a2);
            af[3] = *reinterpret_cast<uint32_t*>(&a3);
            const uint32_t vBase = sVs + (uint32_t)(kk * 16 * HStr) * 2;
            #pragma unroll
            for (int np = 0; np < 4; np++) {
                uint32_t q[4];
                ldsm_x4t(q, vBase + vPair[np]);
                mma_f16(o[2 * np],     af, q);
                mma_f16(o[2 * np + 1], af, q + 2);
            }
        }
    }

    // Epilogue: normalize, write half to concat layout g_Zh[b, s, h*64+dv]
    const int grp = lane >> 2;
    const int tig = lane & 3;
    float inv0 = 1.0f / l_i[0];
    float inv1 = 1.0f / l_i[1];
    int row0 = q0 + r0 + grp;
    #pragma unroll
    for (int nt = 0; nt < 8; nt++) {
        int col = h * 64 + nt * 8 + 2 * tig;
        *reinterpret_cast<__half2*>(
            &g_Zh[((size_t)b * Sn + row0) * 1024 + col]) =
            __floats2half2_rn(o[nt][0] * inv0, o[nt][1] * inv0);
        *reinterpret_cast<__half2*>(
            &g_Zh[((size_t)b * Sn + row0 + 8) * 1024 + col]) =
            __floats2half2_rn(o[nt][2] * inv1, o[nt][3] * inv1);
    }
}

// ---------------------------------------------------------------------------
extern "C" void kernel_launch(void* const* d_in, const int* in_sizes, int n_in,
                              void* d_out, int out_size)
{
    const float* X  = (const float*)d_in[0];
    const float* Wk = (const float*)d_in[1];
    const float* bk = (const float*)d_in[2];
    const float* Wq = (const float*)d_in[3];
    const float* bq = (const float*)d_in[4];
    const float* Wv = (const float*)d_in[5];
    const float* bv = (const float*)d_in[6];
    const float* Wo = (const float*)d_in[7];
    const float* bo = (const float*)d_in[8];
    float* out = (float*)d_out;

    cudaFuncSetAttribute(gemm_mma_kernel<0>,
                         cudaFuncAttributeMaxDynamicSharedMemorySize, GEMM_SMEM);
    cudaFuncSetAttribute(gemm_mma_kernel<1>,
                         cudaFuncAttributeMaxDynamicSharedMemorySize, GEMM_SMEM);
    cudaFuncSetAttribute(attn_mma_kernel,
                         cudaFuncAttributeMaxDynamicSharedMemorySize, ATTN_SMEM);

    prep_kernel<<<5120, 256>>>(X, Wq, Wk, Wv, Wo);
    gemm_mma_kernel<0><<<dim3(24, 32), 256, GEMM_SMEM>>>(
        bq, bk, bv, nullptr, nullptr);
    attn_mma_kernel<<<dim3(Sn / 128, Hn, Bn), 256, ATTN_SMEM>>>();
    gemm_mma_kernel<1><<<dim3(8, 32), 256, GEMM_SMEM>>>(
        bo, nullptr, nullptr, X, out);
}